// round 16
// baseline (speedup 1.0000x reference)
#include <cuda_runtime.h>
#include <cuda_fp16.h>
#include <math.h>
typedef unsigned int uint;
typedef unsigned short ushort;

#define B_   64
#define T_   512
#define H_   1024
#define L_   2
#define G_   4096
#define K2_  2048
#define NBLK 128

// lstm_seq smem plan (float units)
#define WH_OFF 0          // W fp16 fragments: 4096 uint4 = 16384 floats (64 KB)
#define HS_OFF 16384      // full h tile: 64 rows x 1032 halfs = 33024 floats (129 KB)
#define HROW   1032
#define GT_OFF 49408      // gate exchange: 2 x 2112 floats
#define GT_GRP 2112
#define CS_OFF 53632      // cell state: 512 floats
#define SM_FLOATS 54144
#define SM_BYTES  (SM_FLOATS * 4)   // 216,576 B -> 1 block/SM

__device__ float  g_gin[(size_t)B_ * T_ * G_];
__device__ float  g_mid[(size_t)B_ * T_ * H_];
__device__ ushort g_hf[2][B_ * H_];        // h single fp16, ping-pong parity
__device__ unsigned g_grp[256];            // 8 group counters, 128B apart
__device__ unsigned g_root = 0;
__device__ unsigned g_gen = 0;

__device__ __forceinline__ void mma_f16(float4& c, const uint4& a, uint b0, uint b1) {
    asm volatile(
        "mma.sync.aligned.m16n8k16.row.col.f32.f16.f16.f32 "
        "{%0,%1,%2,%3}, {%4,%5,%6,%7}, {%8,%9}, {%0,%1,%2,%3};"
        : "+f"(c.x), "+f"(c.y), "+f"(c.z), "+f"(c.w)
        : "r"(a.x), "r"(a.y), "r"(a.z), "r"(a.w), "r"(b0), "r"(b1));
}
__device__ __forceinline__ uint h2pack(float2 v) {
    __half2 h = __float22half2_rn(v);
    return *(uint*)&h;
}
__device__ __forceinline__ float sigmoidf_(float x) { return __fdividef(1.0f, 1.0f + expf(-x)); }
__device__ __forceinline__ void cp_async16u(const ushort* smem_dst, const ushort* gsrc) {
    unsigned sa = (unsigned)__cvta_generic_to_shared((void*)smem_dst);
    asm volatile("cp.async.cg.shared.global [%0], [%1], 16;" :: "r"(sa), "l"(gsrc));
}

// Tree grid barrier: 8 padded group counters -> root -> release gen.
__device__ __forceinline__ void grid_barrier(int jb) {
    __syncthreads();
    if (threadIdx.x == 0) {
        asm volatile("fence.acq_rel.gpu;" ::: "memory");
        unsigned old;
        asm volatile("ld.relaxed.gpu.u32 %0, [%1];" : "=r"(old) : "l"(&g_gen));
        unsigned prev = atomicAdd(&g_grp[(jb & 7) * 32], 1u);
        bool done = false;
        if (prev == 15u) {
            unsigned pr = atomicAdd(&g_root, 1u);
            if (pr == 7u) {
#pragma unroll
                for (int i = 0; i < 8; i++)
                    asm volatile("st.relaxed.gpu.u32 [%0], %1;"
                                 :: "l"(&g_grp[i * 32]), "r"(0u));
                asm volatile("st.relaxed.gpu.u32 [%0], %1;" :: "l"(&g_root), "r"(0u));
                asm volatile("st.release.gpu.u32 [%0], %1;" :: "l"(&g_gen), "r"(old + 1u));
                done = true;
            }
        }
        if (!done) {
            unsigned cur;
            do { asm volatile("ld.acquire.gpu.u32 %0, [%1];" : "=r"(cur) : "l"(&g_gen)); }
            while (cur == old);
        }
    }
    __syncthreads();
}

// ---------------------------------------------------------------------------
// Input GEMM (single-term fp16) — unchanged from R14 (passing).
// ---------------------------------------------------------------------------
__global__ void __launch_bounds__(256, 2) lstm_in_gemm(
    const float* __restrict__ A, const float* __restrict__ Wl,
    const float* __restrict__ bl, float* __restrict__ C)
{
    __shared__ uint4 Af[512];
    __shared__ uint2 Bf[512];

    const int tid = threadIdx.x, n0 = blockIdx.x * 64, m0 = blockIdx.y * 128;
    const int lane = tid & 31, warp = tid >> 5;
    const int wm = warp >> 1, wn = warp & 1;
    const int g = lane >> 2, tg = lane & 3;

    const size_t rA0 = (size_t)(m0 + warp * 16 + g) * H_;
    const size_t rA1 = rA0 + (size_t)8 * H_;
    const size_t rB0 = (size_t)(n0 + warp * 8 + g) * K2_;

    float2 a0v, a1v, a2v, a3v, b0v, b1v;
    float4 cc[2][4];
#pragma unroll
    for (int i = 0; i < 2; i++)
#pragma unroll
        for (int j = 0; j < 4; j++) cc[i][j] = make_float4(0.f, 0.f, 0.f, 0.f);

#define LOADG(kb_) do {                                       \
    a0v = *(const float2*)&A[rA0 + (kb_) + tg * 2];           \
    a1v = *(const float2*)&A[rA1 + (kb_) + tg * 2];           \
    a2v = *(const float2*)&A[rA0 + (kb_) + 8 + tg * 2];       \
    a3v = *(const float2*)&A[rA1 + (kb_) + 8 + tg * 2];       \
    b0v = *(const float2*)&Wl[rB0 + (kb_) + tg * 2];          \
    b1v = *(const float2*)&Wl[rB0 + (kb_) + 8 + tg * 2];      \
} while (0)

#define STAGE(buf_) do {                                      \
    Af[((buf_) * 8 + warp) * 32 + lane] =                     \
        make_uint4(h2pack(a0v), h2pack(a1v), h2pack(a2v), h2pack(a3v)); \
    Bf[((buf_) * 8 + warp) * 32 + lane] = make_uint2(h2pack(b0v), h2pack(b1v)); \
} while (0)

    LOADG(0);
    STAGE(0);
    __syncthreads();

    for (int it = 0; it < 64; it++) {
        const int buf = it & 1;
        if (it < 63) LOADG((it + 1) * 16);

        uint4 aF0 = Af[(buf * 8 + wm * 2 + 0) * 32 + lane];
        uint4 aF1 = Af[(buf * 8 + wm * 2 + 1) * 32 + lane];
#pragma unroll
        for (int nt = 0; nt < 4; nt++) {
            uint2 bv = Bf[(buf * 8 + wn * 4 + nt) * 32 + lane];
            mma_f16(cc[0][nt], aF0, bv.x, bv.y);
            mma_f16(cc[1][nt], aF1, bv.x, bv.y);
        }
        if (it < 63) STAGE((it + 1) & 1);
        __syncthreads();
    }
#undef LOADG
#undef STAGE

#pragma unroll
    for (int mt = 0; mt < 2; mt++)
#pragma unroll
        for (int nt = 0; nt < 4; nt++) {
            const int row = m0 + wm * 32 + mt * 16 + g;
            const int col = n0 + wn * 32 + nt * 8 + 2 * tg;
            const float2 bias = *(const float2*)&bl[col];
            float4 v = cc[mt][nt];
            *(float2*)&C[(size_t)row * G_ + col] = make_float2(v.x + bias.x, v.y + bias.y);
            *(float2*)&C[(size_t)(row + 8) * G_ + col] = make_float2(v.z + bias.x, v.w + bias.y);
        }
}

// ---------------------------------------------------------------------------
// Persistent recurrence (1-term fp16): full-h staging, 4 syncs per step.
// Block jb: M=32 gate cols, N=64 batch, K=1024. W in smem; h fully staged
// into smem each step (two 64KB halves, second overlaps first-half mma).
// ---------------------------------------------------------------------------
__global__ void __launch_bounds__(256, 1) lstm_seq(
    const float* __restrict__ Wl, const float* __restrict__ gin,
    const float* __restrict__ c0l, const float* __restrict__ h0l,
    ushort* __restrict__ hF0, ushort* __restrict__ hF1,
    float* __restrict__ layer_out, float* __restrict__ outp, int l)
{
    extern __shared__ float sm[];
    uint4*  WsH = (uint4*)(sm + WH_OFF);     // [mt2*64kg][lane32]
    ushort* hs  = (ushort*)(sm + HS_OFF);    // [64 b][1032 halfs]
    float*  gt  = sm + GT_OFF;
    float*  cs  = sm + CS_OFF;

    const int tid = threadIdx.x, jb = blockIdx.x;
    const int lane = tid & 31, warp = tid >> 5;
    const int wn = warp & 3, kw = warp >> 2;

    // --- W fragment staging (once per layer), single fp16
#pragma unroll 1
    for (int q = 0; q < 16; q++) {
        const int fi = q * 256 + tid;
        const int ln = fi & 31, kc = (fi >> 5) & 63, mt = fi >> 11;
        const int colc = mt * 16 + (ln >> 2);
        const int colc8 = colc + 8;
        const int gr  = (colc  >> 3) * H_ + jb * 8 + (colc  & 7);
        const int gr8 = (colc8 >> 3) * H_ + jb * 8 + (colc8 & 7);
        const int k0 = kc * 16 + (ln & 3) * 2;
        const float* w0 = Wl + (size_t)gr  * K2_ + H_;
        const float* w8 = Wl + (size_t)gr8 * K2_ + H_;
        uint p0 = h2pack(*(const float2*)(w0 + k0));
        uint p1 = h2pack(*(const float2*)(w8 + k0));
        uint p2 = h2pack(*(const float2*)(w0 + k0 + 8));
        uint p3 = h2pack(*(const float2*)(w8 + k0 + 8));
        WsH[fi] = make_uint4(p0, p1, p2, p3);
    }
    for (int i = tid; i < 512; i += 256)
        cs[i] = c0l[(i >> 3) * H_ + jb * 8 + (i & 7)];
    // h0 -> parity-0 buffer as single fp16 (this block's k slice)
#pragma unroll
    for (int q = 0; q < 2; q++) {
        const int idx = tid + q * 256;
        const int k = jb * 8 + (idx >> 6), b = idx & 63;
        __half hh = __float2half_rn(h0l[b * H_ + k]);
        hF0[b * 1024 + k] = *(ushort*)&hh;
    }

    const int b_pw = tid & 63;
    const int jj0  = (tid >> 6) * 2;
    const int sb = tid >> 2;                 // staging row 0..63
    const int sq = (tid & 3) * 128;          // quarter offset within a half (halfs)

    for (int t = 0; t < T_; t++) {
        const ushort* rH = (t & 1) ? hF1 : hF0;
        ushort*       wH = (t & 1) ? hF0 : hF1;

        const float* gp = gin + ((size_t)b_pw * T_ + t) * G_ + jb * 8 + jj0;
        float2 pf = __ldg((const float2*)gp);
        float2 pi = __ldg((const float2*)(gp + H_));
        float2 pg = __ldg((const float2*)(gp + 2 * H_));
        float2 po = __ldg((const float2*)(gp + 3 * H_));

        grid_barrier(jb);

        // stage FULL h: two 64KB halves (k<512, k>=512)
        {
            const ushort* srow = rH + sb * 1024;
            ushort* drow = hs + sb * HROW;
#pragma unroll
            for (int s = 0; s < 16; s++)
                cp_async16u(drow + sq + s * 8, srow + sq + s * 8);
            asm volatile("cp.async.commit_group;");
#pragma unroll
            for (int s = 0; s < 16; s++)
                cp_async16u(drow + 512 + sq + s * 8, srow + 512 + sq + s * 8);
            asm volatile("cp.async.commit_group;");
        }

        float4 aHH[2][2];
#pragma unroll
        for (int i = 0; i < 2; i++)
#pragma unroll
            for (int j = 0; j < 2; j++)
                aHH[i][j] = make_float4(0.f, 0.f, 0.f, 0.f);

        const int colA = (wn * 2 + 0) * 8 + (lane >> 2);
        const int colB = (wn * 2 + 1) * 8 + (lane >> 2);
        const int tg2  = (lane & 3) * 2;

        // half 1: chunks 0..7 (k 0..511); half-2 loads still in flight
        asm volatile("cp.async.wait_group 1;");
        __syncthreads();
#pragma unroll
        for (int kt = 0; kt < 8; kt++) {
#pragma unroll
            for (int r = 0; r < 2; r++) {
                const int kg = kt * 4 + 2 * r + kw;
                uint4 aH0 = WsH[kg * 32 + lane];
                uint4 aH1 = WsH[(64 + kg) * 32 + lane];
                const int ko = kg * 16 + tg2;
                uint b0A = *(const uint*)(hs + colA * HROW + ko);
                uint b1A = *(const uint*)(hs + colA * HROW + ko + 8);
                uint b0B = *(const uint*)(hs + colB * HROW + ko);
                uint b1B = *(const uint*)(hs + colB * HROW + ko + 8);
                mma_f16(aHH[0][0], aH0, b0A, b1A);
                mma_f16(aHH[1][0], aH1, b0A, b1A);
                mma_f16(aHH[0][1], aH0, b0B, b1B);
                mma_f16(aHH[1][1], aH1, b0B, b1B);
            }
        }
        // half 2: chunks 8..15 (k 512..1023)
        asm volatile("cp.async.wait_group 0;");
        __syncthreads();
#pragma unroll
        for (int kt = 8; kt < 16; kt++) {
#pragma unroll
            for (int r = 0; r < 2; r++) {
                const int kg = kt * 4 + 2 * r + kw;
                uint4 aH0 = WsH[kg * 32 + lane];
                uint4 aH1 = WsH[(64 + kg) * 32 + lane];
                const int ko = kg * 16 + tg2;
                uint b0A = *(const uint*)(hs + colA * HROW + ko);
                uint b1A = *(const uint*)(hs + colA * HROW + ko + 8);
                uint b0B = *(const uint*)(hs + colB * HROW + ko);
                uint b1B = *(const uint*)(hs + colB * HROW + ko + 8);
                mma_f16(aHH[0][0], aH0, b0A, b1A);
                mma_f16(aHH[1][0], aH1, b0A, b1A);
                mma_f16(aHH[0][1], aH0, b0B, b1B);
                mma_f16(aHH[1][1], aH1, b0B, b1B);
            }
        }
        __syncthreads();   // protect hs reuse + order gt writes below

        // gate partials -> slab (kw groups separate)
        float* slab = gt + kw * GT_GRP;
#pragma unroll
        for (int mt = 0; mt < 2; mt++)
#pragma unroll
            for (int nt = 0; nt < 2; nt++) {
                float4 v = aHH[mt][nt];
                const int colr = mt * 16 + (lane >> 2);
                const int bcol = (wn * 2 + nt) * 8 + tg2;
                *(float2*)&slab[colr * 66 + bcol] = make_float2(v.x, v.y);
                *(float2*)&slab[(colr + 8) * 66 + bcol] = make_float2(v.z, v.w);
            }
        __syncthreads();

        // pointwise: thread owns batch b_pw, gate cols jj0, jj0+1
        float2 c_old = *(float2*)&cs[b_pw * 8 + jj0];
        float co[2] = {c_old.x, c_old.y};
        float gf[2] = {pf.x, pf.y}, gi2[2] = {pi.x, pi.y};
        float gg2[2] = {pg.x, pg.y}, go[2] = {po.x, po.y};
        float hv[2], cv[2];
#pragma unroll
        for (int j = 0; j < 2; j++) {
            const int jj = jj0 + j;
            float xf = gt[jj * 66 + b_pw]        + gt[GT_GRP + jj * 66 + b_pw]        + gf[j];
            float xi = gt[(8 + jj) * 66 + b_pw]  + gt[GT_GRP + (8 + jj) * 66 + b_pw]  + gi2[j];
            float xg = gt[(16 + jj) * 66 + b_pw] + gt[GT_GRP + (16 + jj) * 66 + b_pw] + gg2[j];
            float xo = gt[(24 + jj) * 66 + b_pw] + gt[GT_GRP + (24 + jj) * 66 + b_pw] + go[j];
            float f = sigmoidf_(xf), ig = sigmoidf_(xi);
            float gv = tanhf(xg),    o  = sigmoidf_(xo);
            cv[j] = f * co[j] + ig * gv;
            hv[j] = o * tanhf(cv[j]);
        }
        *(float2*)&cs[b_pw * 8 + jj0] = make_float2(cv[0], cv[1]);
        *(uint*)&wH[b_pw * 1024 + jb * 8 + jj0] = h2pack(make_float2(hv[0], hv[1]));
        *(float2*)&layer_out[((size_t)b_pw * T_ + t) * H_ + jb * 8 + jj0] =
            make_float2(hv[0], hv[1]);
        if (t == T_ - 1) {
            size_t hb2 = (size_t)B_ * T_ * H_ + (size_t)l * B_ * H_ +
                         (size_t)b_pw * H_ + jb * 8 + jj0;
            *(float2*)&outp[hb2] = make_float2(hv[0], hv[1]);
            *(float2*)&outp[hb2 + (size_t)L_ * B_ * H_] = make_float2(cv[0], cv[1]);
        }
    }
}

extern "C" void kernel_launch(void* const* d_in, const int* in_sizes, int n_in,
                              void* d_out, int out_size)
{
    const float* x  = (const float*)d_in[0];
    const float* W  = (const float*)d_in[1];
    const float* bs = (const float*)d_in[2];
    const float* h0 = (const float*)d_in[3];
    const float* c0 = (const float*)d_in[4];
    float* out = (float*)d_out;

    float *gin, *mid;
    ushort* hf;
    cudaGetSymbolAddress((void**)&gin, g_gin);
    cudaGetSymbolAddress((void**)&mid, g_mid);
    cudaGetSymbolAddress((void**)&hf, g_hf);
    ushort* hF0 = hf;
    ushort* hF1 = hf + B_ * H_;

    cudaFuncSetAttribute(lstm_seq, cudaFuncAttributeMaxDynamicSharedMemorySize,
                         SM_BYTES);

    for (int l = 0; l < L_; l++) {
        const float* layer_in  = (l == 0) ? x   : mid;
        float*       layer_out = (l == 0) ? mid : out;
        const float* Wl = W  + (size_t)l * G_ * K2_;
        const float* bl = bs + (size_t)l * G_;

        lstm_in_gemm<<<dim3(64, 256), 256>>>(layer_in, Wl, bl, gin);
        lstm_seq<<<NBLK, 256, SM_BYTES>>>(Wl, gin,
                                          c0 + (size_t)l * B_ * H_,
                                          h0 + (size_t)l * B_ * H_,
                                          hF0, hF1, layer_out, out, l);
    }
}